// round 1
// baseline (speedup 1.0000x reference)
#include <cuda_runtime.h>
#include <math.h>

#define SEQ 4096
#define DIM 768
#define NH  12
#define HD  64
#define NL  12
#define FFD 3072
#define WIN 256
#define EPSF 1e-5f

// ---------------- scratch (static device globals; no runtime allocation) ----
__device__ float g_x[SEQ * DIM];
__device__ float g_q[SEQ * DIM];
__device__ float g_k[SEQ * DIM];
__device__ float g_v[SEQ * DIM];
__device__ float g_a[SEQ * DIM];
__device__ float g_t[SEQ * DIM];
__device__ float g_h[SEQ * FFD];
__device__ int   g_pos[SEQ];

// ---------------- helpers ---------------------------------------------------
__device__ __forceinline__ float gelu_exact(float x) {
    return 0.5f * x * (1.0f + erff(x * 0.70710678118654752f));
}

// block-wide sum over 256 threads; red must be shared float[32]
__device__ __forceinline__ float blk_sum256(float v, float* red) {
    #pragma unroll
    for (int o = 16; o > 0; o >>= 1) v += __shfl_down_sync(0xffffffffu, v, o);
    int w = threadIdx.x >> 5;
    if ((threadIdx.x & 31) == 0) red[w] = v;
    __syncthreads();
    if (threadIdx.x < 32) {
        v = (threadIdx.x < 8) ? red[threadIdx.x] : 0.0f;
        #pragma unroll
        for (int o = 4; o > 0; o >>= 1) v += __shfl_down_sync(0xffffffffu, v, o);
        if (threadIdx.x == 0) red[0] = v;
    }
    __syncthreads();
    float r = red[0];
    __syncthreads();
    return r;
}

// ---------------- pos_ids = cumsum(mask)*mask + 1 ---------------------------
__global__ void pos_kernel(const int* __restrict__ mask, int* __restrict__ pos) {
    __shared__ int ss[1024];
    int t = threadIdx.x;
    int m0 = mask[t * 4 + 0], m1 = mask[t * 4 + 1];
    int m2 = mask[t * 4 + 2], m3 = mask[t * 4 + 3];
    int s = m0 + m1 + m2 + m3;
    ss[t] = s;
    __syncthreads();
    for (int off = 1; off < 1024; off <<= 1) {
        int vprev = (t >= off) ? ss[t - off] : 0;
        __syncthreads();
        ss[t] += vprev;
        __syncthreads();
    }
    int run = ss[t] - s;  // exclusive prefix
    run += m0; pos[t * 4 + 0] = run * m0 + 1;
    run += m1; pos[t * 4 + 1] = run * m1 + 1;
    run += m2; pos[t * 4 + 2] = run * m2 + 1;
    run += m3; pos[t * 4 + 3] = run * m3 + 1;
}

// ---------------- embedding + layernorm (one block per token row) -----------
__global__ void embed_ln_kernel(const int* __restrict__ ids, const int* __restrict__ pos,
                                const float* __restrict__ ew, const float* __restrict__ ep,
                                const float* __restrict__ et, const float* __restrict__ g,
                                const float* __restrict__ b, float* __restrict__ x) {
    __shared__ float red[32];
    int srow = blockIdx.x;
    int t = threadIdx.x;
    int wid = ids[srow];
    int pid = pos[srow];
    float val[3];
    #pragma unroll
    for (int r = 0; r < 3; r++) {
        int i = t + r * 256;
        val[r] = ew[(size_t)wid * DIM + i] + ep[(size_t)pid * DIM + i] + et[i];
    }
    float mu = blk_sum256(val[0] + val[1] + val[2], red) * (1.0f / DIM);
    float vs = 0.0f;
    #pragma unroll
    for (int r = 0; r < 3; r++) { float d = val[r] - mu; vs += d * d; }
    float var = blk_sum256(vs, red) * (1.0f / DIM);
    float rs = rsqrtf(var + EPSF);
    #pragma unroll
    for (int r = 0; r < 3; r++) {
        int i = t + r * 256;
        x[(size_t)srow * DIM + i] = (val[r] - mu) * rs * g[i] + b[i];
    }
}

// ---------------- x = LN(x + delta) -----------------------------------------
__global__ void lnres_kernel(float* __restrict__ x, const float* __restrict__ delta,
                             const float* __restrict__ g, const float* __restrict__ b) {
    __shared__ float red[32];
    int srow = blockIdx.x;
    int t = threadIdx.x;
    float val[3];
    #pragma unroll
    for (int r = 0; r < 3; r++) {
        int i = t + r * 256;
        val[r] = x[(size_t)srow * DIM + i] + delta[(size_t)srow * DIM + i];
    }
    float mu = blk_sum256(val[0] + val[1] + val[2], red) * (1.0f / DIM);
    float vs = 0.0f;
    #pragma unroll
    for (int r = 0; r < 3; r++) { float d = val[r] - mu; vs += d * d; }
    float var = blk_sum256(vs, red) * (1.0f / DIM);
    float rs = rsqrtf(var + EPSF);
    #pragma unroll
    for (int r = 0; r < 3; r++) {
        int i = t + r * 256;
        x[(size_t)srow * DIM + i] = (val[r] - mu) * rs * g[i] + b[i];
    }
}

// ---------------- SGEMM: C[M,N] = A[M,K] @ B[K,N] + bias, optional GELU -----
// 128x128 block tile, BK=16, 256 threads, 8x8 per thread.
template <int ACT>
__global__ void sgemm_kernel(const float* __restrict__ A, const float* __restrict__ B,
                             const float* __restrict__ bias, float* __restrict__ C,
                             int M, int N, int K) {
    __shared__ float As[16][128];
    __shared__ float Bs[16][128];
    const int bx = blockIdx.x;   // N tile
    const int by = blockIdx.y;   // M tile
    const int tid = threadIdx.x; // 256
    const int tx = tid & 15;
    const int ty = tid >> 4;

    const float* Ab = A + (size_t)by * 128 * K;
    const float* Bb = B + (size_t)bx * 128;

    float acc[8][8];
    #pragma unroll
    for (int i = 0; i < 8; i++)
        #pragma unroll
        for (int j = 0; j < 8; j++) acc[i][j] = 0.0f;

    for (int k0 = 0; k0 < K; k0 += 16) {
        #pragma unroll
        for (int it = 0; it < 2; it++) {
            int f = tid + it * 256;        // 0..511 (512 float4 per tile)
            // A tile: 128 rows x 16 cols
            int r = f >> 2;
            int c4 = (f & 3) * 4;
            float4 a4 = *(const float4*)(Ab + (size_t)r * K + k0 + c4);
            As[c4 + 0][r] = a4.x;
            As[c4 + 1][r] = a4.y;
            As[c4 + 2][r] = a4.z;
            As[c4 + 3][r] = a4.w;
            // B tile: 16 rows x 128 cols
            int r2 = f >> 5;
            int c2 = (f & 31) * 4;
            float4 b4 = *(const float4*)(Bb + (size_t)(k0 + r2) * N + c2);
            *(float4*)&Bs[r2][c2] = b4;
        }
        __syncthreads();
        #pragma unroll
        for (int kk = 0; kk < 16; kk++) {
            float ar[8], br[8];
            #pragma unroll
            for (int i = 0; i < 8; i++) ar[i] = As[kk][ty * 8 + i];
            #pragma unroll
            for (int j = 0; j < 8; j++) br[j] = Bs[kk][tx * 8 + j];
            #pragma unroll
            for (int i = 0; i < 8; i++)
                #pragma unroll
                for (int j = 0; j < 8; j++) acc[i][j] += ar[i] * br[j];
        }
        __syncthreads();
    }

    int colbase = bx * 128 + tx * 8;
    float bsr[8];
    #pragma unroll
    for (int j = 0; j < 8; j++) bsr[j] = bias[colbase + j];
    #pragma unroll
    for (int i = 0; i < 8; i++) {
        int row = by * 128 + ty * 8 + i;
        float4 o0, o1;
        float vals[8];
        #pragma unroll
        for (int j = 0; j < 8; j++) {
            float v = acc[i][j] + bsr[j];
            if (ACT == 1) v = gelu_exact(v);
            vals[j] = v;
        }
        o0 = make_float4(vals[0], vals[1], vals[2], vals[3]);
        o1 = make_float4(vals[4], vals[5], vals[6], vals[7]);
        *(float4*)(C + (size_t)row * N + colbase) = o0;
        *(float4*)(C + (size_t)row * N + colbase + 4) = o1;
    }
}

// ---------------- sliding-window attention (flash-style online softmax) -----
// grid: (SEQ/128, NH), block: 128 threads, 1 query per thread.
__global__ void attn_kernel(const float* __restrict__ q, const float* __restrict__ k,
                            const float* __restrict__ v, const int* __restrict__ mask,
                            float* __restrict__ o) {
    const int h = blockIdx.y;
    const int q0 = blockIdx.x * 128;
    const int tid = threadIdx.x;
    const int qi = q0 + tid;

    __shared__ float Ks[32][64];
    __shared__ float Vs[32][64];
    __shared__ int msk[32];

    float qr[64];
    const float scale = 0.125f;  // 1/sqrt(64)
    #pragma unroll
    for (int d = 0; d < 64; d++) qr[d] = q[(size_t)qi * DIM + h * 64 + d] * scale;

    float acc[64];
    #pragma unroll
    for (int d = 0; d < 64; d++) acc[d] = 0.0f;
    float m = -1e30f, l = 0.0f;

    const int kstart = q0 - WIN;
    const int kend = q0 + 127 + WIN;
    for (int c = kstart; c <= kend; c += 32) {
        #pragma unroll
        for (int r = 0; r < 4; r++) {
            int f = tid + r * 128;         // 0..511
            int row = f >> 4;
            int col = (f & 15) * 4;
            int kp = c + row;
            float4 kv, vv;
            if (kp >= 0 && kp < SEQ) {
                kv = *(const float4*)(k + (size_t)kp * DIM + h * 64 + col);
                vv = *(const float4*)(v + (size_t)kp * DIM + h * 64 + col);
            } else {
                kv = make_float4(0.f, 0.f, 0.f, 0.f);
                vv = kv;
            }
            *(float4*)&Ks[row][col] = kv;
            *(float4*)&Vs[row][col] = vv;
        }
        if (tid < 32) {
            int kp = c + tid;
            msk[tid] = (kp >= 0 && kp < SEQ) ? mask[kp] : 0;
        }
        __syncthreads();

        #pragma unroll 1
        for (int j = 0; j < 32; j++) {
            int kp = c + j;
            bool valid = msk[j] && (kp >= qi - WIN) && (kp <= qi + WIN);
            if (valid) {
                float s = 0.0f;
                #pragma unroll
                for (int d = 0; d < 64; d++) s += qr[d] * Ks[j][d];
                if (s > m) {
                    float sc = __expf(m - s);
                    #pragma unroll
                    for (int d = 0; d < 64; d++) acc[d] = acc[d] * sc + Vs[j][d];
                    l = l * sc + 1.0f;
                    m = s;
                } else {
                    float p = __expf(s - m);
                    #pragma unroll
                    for (int d = 0; d < 64; d++) acc[d] += p * Vs[j][d];
                    l += p;
                }
            }
        }
        __syncthreads();
    }

    float inv = (l > 0.0f) ? (1.0f / l) : 0.0f;
    #pragma unroll
    for (int d = 0; d < 64; d += 4) {
        float4 ov = make_float4(acc[d] * inv, acc[d + 1] * inv, acc[d + 2] * inv, acc[d + 3] * inv);
        *(float4*)(o + (size_t)qi * DIM + h * 64 + d) = ov;
    }
}

// ---------------- classification heads (768 -> 512 relu -> nout) ------------
__global__ void head_kernel(const float* __restrict__ x, const float* __restrict__ W1,
                            const float* __restrict__ b1, const float* __restrict__ W2,
                            const float* __restrict__ b2, float* __restrict__ out, int nout) {
    __shared__ float xs[768];
    __shared__ float hsm[512];
    int t = threadIdx.x;  // 512
    for (int i = t; i < 768; i += 512) xs[i] = x[i];
    __syncthreads();
    float acc = b1[t];
    for (int kk = 0; kk < 768; kk++) acc += xs[kk] * W1[(size_t)kk * 512 + t];
    hsm[t] = fmaxf(acc, 0.0f);
    __syncthreads();
    if (t < nout) {
        float ov = b2[t];
        for (int kk = 0; kk < 512; kk++) ov += hsm[kk] * W2[(size_t)kk * nout + t];
        out[t] = ov;
    }
}

// ---------------- host launcher ---------------------------------------------
extern "C" void kernel_launch(void* const* d_in, const int* in_sizes, int n_in,
                              void* d_out, int out_size) {
    const int*   ids      = (const int*)d_in[0];
    const int*   mask     = (const int*)d_in[1];
    const float* emb_word = (const float*)d_in[2];
    const float* emb_pos  = (const float*)d_in[3];
    const float* emb_type = (const float*)d_in[4];
    const float* emb_g    = (const float*)d_in[5];
    const float* emb_b    = (const float*)d_in[6];
    const float* Wq = (const float*)d_in[7];
    const float* bq = (const float*)d_in[8];
    const float* Wk = (const float*)d_in[9];
    const float* bk = (const float*)d_in[10];
    const float* Wv = (const float*)d_in[11];
    const float* bv = (const float*)d_in[12];
    const float* Wo = (const float*)d_in[13];
    const float* bo = (const float*)d_in[14];
    const float* ln1g = (const float*)d_in[15];
    const float* ln1b = (const float*)d_in[16];
    const float* W1 = (const float*)d_in[17];
    const float* b1 = (const float*)d_in[18];
    const float* W2 = (const float*)d_in[19];
    const float* b2 = (const float*)d_in[20];
    const float* ln2g = (const float*)d_in[21];
    const float* ln2b = (const float*)d_in[22];
    const float* cW1 = (const float*)d_in[23];
    const float* cb1 = (const float*)d_in[24];
    const float* cW2 = (const float*)d_in[25];
    const float* cb2 = (const float*)d_in[26];
    const float* dW1 = (const float*)d_in[27];
    const float* db1 = (const float*)d_in[28];
    const float* dW2 = (const float*)d_in[29];
    const float* db2 = (const float*)d_in[30];
    float* out = (float*)d_out;

    float *x, *q, *k, *v, *a, *t, *hbuf;
    int* pos;
    cudaGetSymbolAddress((void**)&x, g_x);
    cudaGetSymbolAddress((void**)&q, g_q);
    cudaGetSymbolAddress((void**)&k, g_k);
    cudaGetSymbolAddress((void**)&v, g_v);
    cudaGetSymbolAddress((void**)&a, g_a);
    cudaGetSymbolAddress((void**)&t, g_t);
    cudaGetSymbolAddress((void**)&hbuf, g_h);
    cudaGetSymbolAddress((void**)&pos, g_pos);

    pos_kernel<<<1, 1024>>>(mask, pos);
    embed_ln_kernel<<<SEQ, 256>>>(ids, pos, emb_word, emb_pos, emb_type, emb_g, emb_b, x);

    dim3 g768(DIM / 128, SEQ / 128);    // (6, 32)
    dim3 g3072(FFD / 128, SEQ / 128);   // (24, 32)
    dim3 gattn(SEQ / 128, NH);          // (32, 12)

    for (int i = 0; i < NL; i++) {
        const float* wq = Wq + (size_t)i * DIM * DIM;
        const float* wk = Wk + (size_t)i * DIM * DIM;
        const float* wv = Wv + (size_t)i * DIM * DIM;
        const float* wo = Wo + (size_t)i * DIM * DIM;
        const float* w1 = W1 + (size_t)i * DIM * FFD;
        const float* w2 = W2 + (size_t)i * FFD * DIM;

        sgemm_kernel<0><<<g768, 256>>>(x, wq, bq + i * DIM, q, SEQ, DIM, DIM);
        sgemm_kernel<0><<<g768, 256>>>(x, wk, bk + i * DIM, k, SEQ, DIM, DIM);
        sgemm_kernel<0><<<g768, 256>>>(x, wv, bv + i * DIM, v, SEQ, DIM, DIM);
        attn_kernel<<<gattn, 128>>>(q, k, v, mask, a);
        sgemm_kernel<0><<<g768, 256>>>(a, wo, bo + i * DIM, t, SEQ, DIM, DIM);
        lnres_kernel<<<SEQ, 256>>>(x, t, ln1g + i * DIM, ln1b + i * DIM);
        sgemm_kernel<1><<<g3072, 256>>>(x, w1, b1 + i * FFD, hbuf, SEQ, FFD, DIM);
        sgemm_kernel<0><<<g768, 256>>>(hbuf, w2, b2 + i * DIM, t, SEQ, DIM, FFD);
        lnres_kernel<<<SEQ, 256>>>(x, t, ln2g + i * DIM, ln2b + i * DIM);
    }

    head_kernel<<<1, 512>>>(x, cW1, cb1, cW2, cb2, out, 5);
    head_kernel<<<1, 512>>>(x, dW1, db1, dW2, db2, out + 5, 10);
}